// round 5
// baseline (speedup 1.0000x reference)
#include <cuda_runtime.h>
#include <math.h>

// AttentionAggregator: warp-per-row, streaming-dot + reload-aggregate.
// features: [100000, 256] f32; nodes: [4096] i32; unique_ids: [16384] i32;
// neigh_idx: [4096, 10] i32. out: [4096, 256] f32.
//
// One warp per node row, no __syncthreads. Pass 1 streams the 10 embed rows
// through registers computing dot products (data discarded -> low register
// residency). Softmax with duplicate-column dedup (dense mask's .set(1.0)
// counts repeats once) is computed redundantly per lane. Pass 2 reloads the
// rows (L1/L2-hot) for the weighted sum. __launch_bounds__(256,4) caps regs
// at 64 -> 32 warps/SM, doubling latency-hiding vs the register-resident
// version while keeping per-warp MLP high.

#define N_NODES 4096
#define FDIM    256
#define NSAMP   10
#define WARPS_PER_BLOCK 8
#define ROWS_PER_BLOCK  WARPS_PER_BLOCK

__global__ __launch_bounds__(256, 4)
void attn_agg_kernel(const float* __restrict__ feat,
                     const int*   __restrict__ nodes,
                     const int*   __restrict__ uids,
                     const int*   __restrict__ nidx,
                     float*       __restrict__ out)
{
    const int warp = threadIdx.x >> 5;
    const int lane = threadIdx.x & 31;
    const int row  = blockIdx.x * ROWS_PER_BLOCK + warp;

    // --- index chain (warp-uniform) ---
    int cols[NSAMP];
    #pragma unroll
    for (int s = 0; s < NSAMP; s++)
        cols[s] = nidx[row * NSAMP + s];

    int uid[NSAMP];
    #pragma unroll
    for (int s = 0; s < NSAMP; s++)
        uid[s] = uids[cols[s]];

    // Duplicate-column mask (dense mask counts repeated (row,col) once).
    unsigned dupmask = 0;
    #pragma unroll
    for (int s = 1; s < NSAMP; s++) {
        bool d = false;
        #pragma unroll
        for (int t = 0; t < NSAMP; t++)
            if (t < s) d |= (cols[t] == cols[s]);
        if (d) dupmask |= (1u << s);
    }

    const int node = nodes[row];
    const float4* qp = (const float4*)(feat + (size_t)node * FDIM);
    const float4 q0 = qp[lane];
    const float4 q1 = qp[lane + 32];

    // --- pass 1: stream rows through registers, keep only dot partials ---
    float dots[NSAMP];
    #pragma unroll
    for (int s = 0; s < NSAMP; s++) {
        const float4* ep = (const float4*)(feat + (size_t)uid[s] * FDIM);
        const float4 a = ep[lane];
        const float4 b = ep[lane + 32];
        dots[s] = a.x * q0.x + a.y * q0.y + a.z * q0.z + a.w * q0.w
                + b.x * q1.x + b.y * q1.y + b.z * q1.z + b.w * q1.w;
    }

    // Butterfly-reduce all 10 dots (independent chains pipeline well).
    #pragma unroll
    for (int s = 0; s < NSAMP; s++) {
        float a = dots[s];
        #pragma unroll
        for (int o = 16; o; o >>= 1)
            a += __shfl_xor_sync(0xffffffffu, a, o);
        dots[s] = a;
    }

    // --- softmax over distinct columns (redundant per lane) ---
    float m = -INFINITY;
    #pragma unroll
    for (int s = 0; s < NSAMP; s++)
        if (!((dupmask >> s) & 1u)) m = fmaxf(m, dots[s]);

    float sum = 0.f;
    #pragma unroll
    for (int s = 0; s < NSAMP; s++) {
        float e = ((dupmask >> s) & 1u) ? 0.f : __expf(dots[s] - m);
        dots[s] = e;
        sum += e;
    }
    const float inv = 1.f / sum;

    // --- pass 2: reload rows (L1/L2-hot), weighted accumulate ---
    float4 o0 = make_float4(0.f, 0.f, 0.f, 0.f);
    float4 o1 = make_float4(0.f, 0.f, 0.f, 0.f);
    #pragma unroll
    for (int s = 0; s < NSAMP; s++) {
        const float4* ep = (const float4*)(feat + (size_t)uid[s] * FDIM);
        const float4 a = ep[lane];
        const float4 b = ep[lane + 32];
        const float ws = dots[s] * inv;
        o0.x += ws * a.x;  o0.y += ws * a.y;
        o0.z += ws * a.z;  o0.w += ws * a.w;
        o1.x += ws * b.x;  o1.y += ws * b.y;
        o1.z += ws * b.z;  o1.w += ws * b.w;
    }

    float4* op = (float4*)(out + (size_t)row * FDIM);
    op[lane]      = o0;
    op[lane + 32] = o1;
}

extern "C" void kernel_launch(void* const* d_in, const int* in_sizes, int n_in,
                              void* d_out, int out_size)
{
    const float* feat  = (const float*)d_in[0];
    const int*   nodes = (const int*)  d_in[1];
    const int*   uids  = (const int*)  d_in[2];
    const int*   nidx  = (const int*)  d_in[3];
    float*       out   = (float*)d_out;
    (void)in_sizes; (void)n_in; (void)out_size;

    attn_agg_kernel<<<N_NODES / ROWS_PER_BLOCK, WARPS_PER_BLOCK * 32>>>(
        feat, nodes, uids, nidx, out);
}

// round 6
// speedup vs baseline: 1.3721x; 1.3721x over previous
#include <cuda_runtime.h>
#include <math.h>

// AttentionAggregator: 2 rows per warp, fully register-resident.
// features: [100000, 256] f32; nodes: [4096] i32; unique_ids: [16384] i32;
// neigh_idx: [4096, 10] i32. out: [4096, 256] f32.
//
// Evidence-driven shape: per-warp MLP is the controlling variable (R2>R3>R4
// trend), so go fatter: each warp owns TWO adjacent node rows. Both index
// chains issue together (80B contiguous nidx chunk -> 5 uniform int4 loads),
// then 44 independent LDG.128 bring both q rows + 20 embed rows into
// registers. Softmax with duplicate-column dedup per row (dense mask's
// .set(1.0) counts repeats once), aggregation pure register FMA, no
// __syncthreads anywhere.

#define N_NODES 4096
#define FDIM    256
#define NSAMP   10
#define WARPS_PER_BLOCK 4
#define ROWS_PER_WARP   2
#define ROWS_PER_BLOCK  (WARPS_PER_BLOCK * ROWS_PER_WARP)

__global__ __launch_bounds__(WARPS_PER_BLOCK * 32)
void attn_agg_kernel(const float* __restrict__ feat,
                     const int*   __restrict__ nodes,
                     const int*   __restrict__ uids,
                     const int*   __restrict__ nidx,
                     float*       __restrict__ out)
{
    const int warp = threadIdx.x >> 5;
    const int lane = threadIdx.x & 31;
    const int row0 = (blockIdx.x * WARPS_PER_BLOCK + warp) * ROWS_PER_WARP;

    // --- index chain for BOTH rows, issued together ---
    // 20 contiguous ints (80B, 16B-aligned since row0 is even): 5x int4.
    int cols[2 * NSAMP];
    {
        const int4* np = (const int4*)(nidx + (size_t)row0 * NSAMP);
        #pragma unroll
        for (int i = 0; i < 5; i++) {
            int4 v = np[i];
            cols[4 * i + 0] = v.x;
            cols[4 * i + 1] = v.y;
            cols[4 * i + 2] = v.z;
            cols[4 * i + 3] = v.w;
        }
    }

    int uid[2 * NSAMP];
    #pragma unroll
    for (int s = 0; s < 2 * NSAMP; s++)
        uid[s] = uids[cols[s]];

    // Per-row duplicate-column masks (dense mask counts repeated cols once).
    unsigned dup[2] = {0u, 0u};
    #pragma unroll
    for (int r = 0; r < 2; r++) {
        #pragma unroll
        for (int s = 1; s < NSAMP; s++) {
            bool d = false;
            #pragma unroll
            for (int t = 0; t < NSAMP; t++)
                if (t < s) d |= (cols[r * NSAMP + t] == cols[r * NSAMP + s]);
            if (d) dup[r] |= (1u << s);
        }
    }

    // node ids for the pair: contiguous 8B, aligned (row0 even).
    const int2 nn = *(const int2*)(nodes + row0);
    const int node[2] = {nn.x, nn.y};

    // --- bulk loads: 2 q rows + 20 embed rows = 44 independent LDG.128 ---
    float4 q0[2], q1[2];
    #pragma unroll
    for (int r = 0; r < 2; r++) {
        const float4* qp = (const float4*)(feat + (size_t)node[r] * FDIM);
        q0[r] = qp[lane];
        q1[r] = qp[lane + 32];
    }

    float4 e0[2][NSAMP], e1[2][NSAMP];
    #pragma unroll
    for (int r = 0; r < 2; r++) {
        #pragma unroll
        for (int s = 0; s < NSAMP; s++) {
            const float4* ep =
                (const float4*)(feat + (size_t)uid[r * NSAMP + s] * FDIM);
            e0[r][s] = ep[lane];
            e1[r][s] = ep[lane + 32];
        }
    }

    // --- dots + butterfly reduce (20 independent reduction chains) ---
    float dots[2][NSAMP];
    #pragma unroll
    for (int r = 0; r < 2; r++) {
        #pragma unroll
        for (int s = 0; s < NSAMP; s++) {
            float a = e0[r][s].x * q0[r].x + e0[r][s].y * q0[r].y
                    + e0[r][s].z * q0[r].z + e0[r][s].w * q0[r].w
                    + e1[r][s].x * q1[r].x + e1[r][s].y * q1[r].y
                    + e1[r][s].z * q1[r].z + e1[r][s].w * q1[r].w;
            #pragma unroll
            for (int o = 16; o; o >>= 1)
                a += __shfl_xor_sync(0xffffffffu, a, o);
            dots[r][s] = a;
        }
    }

    // --- per-row softmax (redundant per lane) + aggregation + store ---
    #pragma unroll
    for (int r = 0; r < 2; r++) {
        float m = -INFINITY;
        #pragma unroll
        for (int s = 0; s < NSAMP; s++)
            if (!((dup[r] >> s) & 1u)) m = fmaxf(m, dots[r][s]);

        float sum = 0.f;
        #pragma unroll
        for (int s = 0; s < NSAMP; s++) {
            float e = ((dup[r] >> s) & 1u) ? 0.f : __expf(dots[r][s] - m);
            dots[r][s] = e;
            sum += e;
        }
        const float inv = 1.f / sum;

        float4 o0 = make_float4(0.f, 0.f, 0.f, 0.f);
        float4 o1 = make_float4(0.f, 0.f, 0.f, 0.f);
        #pragma unroll
        for (int s = 0; s < NSAMP; s++) {
            const float ws = dots[r][s] * inv;
            o0.x += ws * e0[r][s].x;  o0.y += ws * e0[r][s].y;
            o0.z += ws * e0[r][s].z;  o0.w += ws * e0[r][s].w;
            o1.x += ws * e1[r][s].x;  o1.y += ws * e1[r][s].y;
            o1.z += ws * e1[r][s].z;  o1.w += ws * e1[r][s].w;
        }

        float4* op = (float4*)(out + (size_t)(row0 + r) * FDIM);
        op[lane]      = o0;
        op[lane + 32] = o1;
    }
}

extern "C" void kernel_launch(void* const* d_in, const int* in_sizes, int n_in,
                              void* d_out, int out_size)
{
    const float* feat  = (const float*)d_in[0];
    const int*   nodes = (const int*)  d_in[1];
    const int*   uids  = (const int*)  d_in[2];
    const int*   nidx  = (const int*)  d_in[3];
    float*       out   = (float*)d_out;
    (void)in_sizes; (void)n_in; (void)out_size;

    attn_agg_kernel<<<N_NODES / ROWS_PER_BLOCK, WARPS_PER_BLOCK * 32>>>(
        feat, nodes, uids, nidx, out);
}

// round 8
// speedup vs baseline: 1.4217x; 1.0361x over previous
#include <cuda_runtime.h>
#include <cstdint>
#include <math.h>

// AttentionAggregator: 2 rows/warp — row A register-resident, row B staged to
// SMEM via cp.async. Rationale: measured dur*inflight-bytes is constant
// (Little's law); RF caps held-load bytes at ~200KB/SM, so SMEM is recruited
// as a second in-flight reservoir through LDGSTS (no registers held).
// features: [100000, 256] f32; nodes: [4096] i32; unique_ids: [16384] i32;
// neigh_idx: [4096, 10] i32. out: [4096, 256] f32.

#define N_NODES 4096
#define FDIM    256
#define NSAMP   10
#define WARPS_PER_BLOCK 4
#define ROWS_PER_BLOCK  (WARPS_PER_BLOCK * 2)
#define SM_ROW_F4 64                      // 256 floats = 64 float4 per row
#define SM_WARP_F4 ((1 + NSAMP) * SM_ROW_F4)   // q_B + 10 embed rows

__device__ __forceinline__ void cp_async16(unsigned int dst, const void* src) {
    asm volatile("cp.async.cg.shared.global [%0], [%1], 16;"
                 :: "r"(dst), "l"(src));
}

__global__ __launch_bounds__(WARPS_PER_BLOCK * 32)
void attn_agg_kernel(const float* __restrict__ feat,
                     const int*   __restrict__ nodes,
                     const int*   __restrict__ uids,
                     const int*   __restrict__ nidx,
                     float*       __restrict__ out)
{
    const int warp = threadIdx.x >> 5;
    const int lane = threadIdx.x & 31;
    const int row0 = (blockIdx.x * WARPS_PER_BLOCK + warp) * 2;  // A=row0, B=row0+1

    __shared__ float4 sbuf[WARPS_PER_BLOCK][SM_WARP_F4];   // 45056 B
    float4* wbuf = sbuf[warp];
    const unsigned int sbase = (unsigned int)__cvta_generic_to_shared(wbuf);

    // --- indices for BOTH rows, issued together (80B contiguous nidx) ---
    int cols[2 * NSAMP];
    {
        const int4* np = (const int4*)(nidx + (size_t)row0 * NSAMP);
        #pragma unroll
        for (int i = 0; i < 5; i++) {
            int4 v = np[i];
            cols[4*i+0] = v.x; cols[4*i+1] = v.y;
            cols[4*i+2] = v.z; cols[4*i+3] = v.w;
        }
    }
    int uid[2 * NSAMP];
    #pragma unroll
    for (int s = 0; s < 2 * NSAMP; s++)
        uid[s] = uids[cols[s]];

    // Per-row duplicate-column masks (dense mask counts repeated cols once).
    unsigned dup[2] = {0u, 0u};
    #pragma unroll
    for (int r = 0; r < 2; r++)
        #pragma unroll
        for (int s = 1; s < NSAMP; s++) {
            bool d = false;
            #pragma unroll
            for (int t = 0; t < NSAMP; t++)
                if (t < s) d |= (cols[r*NSAMP+t] == cols[r*NSAMP+s]);
            if (d) dup[r] |= (1u << s);
        }

    const int2 nn = *(const int2*)(nodes + row0);

    // --- fire row B into SMEM: 22 cp.async per lane, zero regs held ---
    {
        const float* qB = feat + (size_t)nn.y * FDIM;
        cp_async16(sbase + (unsigned int)lane * 16u,        qB + lane * 4);
        cp_async16(sbase + (unsigned int)(lane + 32) * 16u, qB + (lane + 32) * 4);
        #pragma unroll
        for (int s = 0; s < NSAMP; s++) {
            const float* eB = feat + (size_t)uid[NSAMP + s] * FDIM;
            const unsigned int off = sbase + (unsigned int)(1 + s) * 1024u;
            cp_async16(off + (unsigned int)lane * 16u,        eB + lane * 4);
            cp_async16(off + (unsigned int)(lane + 32) * 16u, eB + (lane + 32) * 4);
        }
        asm volatile("cp.async.commit_group;" ::: "memory");
    }

    // --- row A: register-resident (22 independent LDG.128) ---
    const float4* qpA = (const float4*)(feat + (size_t)nn.x * FDIM);
    const float4 qA0 = qpA[lane];
    const float4 qA1 = qpA[lane + 32];

    float4 a0[NSAMP], a1[NSAMP];
    #pragma unroll
    for (int s = 0; s < NSAMP; s++) {
        const float4* ep = (const float4*)(feat + (size_t)uid[s] * FDIM);
        a0[s] = ep[lane];
        a1[s] = ep[lane + 32];
    }

    float dots[NSAMP];
    #pragma unroll
    for (int s = 0; s < NSAMP; s++) {
        float a = a0[s].x*qA0.x + a0[s].y*qA0.y + a0[s].z*qA0.z + a0[s].w*qA0.w
                + a1[s].x*qA1.x + a1[s].y*qA1.y + a1[s].z*qA1.z + a1[s].w*qA1.w;
        #pragma unroll
        for (int o = 16; o; o >>= 1)
            a += __shfl_xor_sync(0xffffffffu, a, o);
        dots[s] = a;
    }

    // softmax A (redundant per lane) + aggregate + store
    {
        float m = -INFINITY;
        #pragma unroll
        for (int s = 0; s < NSAMP; s++)
            if (!((dup[0] >> s) & 1u)) m = fmaxf(m, dots[s]);
        float sum = 0.f;
        #pragma unroll
        for (int s = 0; s < NSAMP; s++) {
            float e = ((dup[0] >> s) & 1u) ? 0.f : __expf(dots[s] - m);
            dots[s] = e; sum += e;
        }
        const float inv = 1.f / sum;

        float4 o0 = make_float4(0.f,0.f,0.f,0.f);
        float4 o1 = make_float4(0.f,0.f,0.f,0.f);
        #pragma unroll
        for (int s = 0; s < NSAMP; s++) {
            const float ws = dots[s] * inv;
            o0.x += ws*a0[s].x; o0.y += ws*a0[s].y;
            o0.z += ws*a0[s].z; o0.w += ws*a0[s].w;
            o1.x += ws*a1[s].x; o1.y += ws*a1[s].y;
            o1.z += ws*a1[s].z; o1.w += ws*a1[s].w;
        }
        float4* op = (float4*)(out + (size_t)row0 * FDIM);
        op[lane]      = o0;
        op[lane + 32] = o1;
    }

    // --- row B: compute from SMEM (each lane reads back its own copies) ---
    asm volatile("cp.async.wait_group 0;" ::: "memory");
    __syncwarp();

    const float4 qB0 = wbuf[lane];
    const float4 qB1 = wbuf[lane + 32];

    #pragma unroll
    for (int s = 0; s < NSAMP; s++) {
        const float4 b0 = wbuf[(1 + s) * SM_ROW_F4 + lane];
        const float4 b1 = wbuf[(1 + s) * SM_ROW_F4 + lane + 32];
        float a = b0.x*qB0.x + b0.y*qB0.y + b0.z*qB0.z + b0.w*qB0.w
                + b1.x*qB1.x + b1.y*qB1.y + b1.z*qB1.z + b1.w*qB1.w;
        #pragma unroll
        for (int o = 16; o; o >>= 1)
            a += __shfl_xor_sync(0xffffffffu, a, o);
        dots[s] = a;
    }

    {
        float m = -INFINITY;
        #pragma unroll
        for (int s = 0; s < NSAMP; s++)
            if (!((dup[1] >> s) & 1u)) m = fmaxf(m, dots[s]);
        float sum = 0.f;
        #pragma unroll
        for (int s = 0; s < NSAMP; s++) {
            float e = ((dup[1] >> s) & 1u) ? 0.f : __expf(dots[s] - m);
            dots[s] = e; sum += e;
        }
        const float inv = 1.f / sum;

        float4 o0 = make_float4(0.f,0.f,0.f,0.f);
        float4 o1 = make_float4(0.f,0.f,0.f,0.f);
        #pragma unroll
        for (int s = 0; s < NSAMP; s++) {
            const float ws = dots[s] * inv;
            const float4 b0 = wbuf[(1 + s) * SM_ROW_F4 + lane];
            const float4 b1 = wbuf[(1 + s) * SM_ROW_F4 + lane + 32];
            o0.x += ws*b0.x; o0.y += ws*b0.y;
            o0.z += ws*b0.z; o0.w += ws*b0.w;
            o1.x += ws*b1.x; o1.y += ws*b1.y;
            o1.z += ws*b1.z; o1.w += ws*b1.w;
        }
        float4* op = (float4*)(out + (size_t)(row0 + 1) * FDIM);
        op[lane]      = o0;
        op[lane + 32] = o1;
    }
}

extern "C" void kernel_launch(void* const* d_in, const int* in_sizes, int n_in,
                              void* d_out, int out_size)
{
    const float* feat  = (const float*)d_in[0];
    const int*   nodes = (const int*)  d_in[1];
    const int*   uids  = (const int*)  d_in[2];
    const int*   nidx  = (const int*)  d_in[3];
    float*       out   = (float*)d_out;
    (void)in_sizes; (void)n_in; (void)out_size;

    attn_agg_kernel<<<N_NODES / ROWS_PER_BLOCK, WARPS_PER_BLOCK * 32>>>(
        feat, nodes, uids, nidx, out);
}